// round 7
// baseline (speedup 1.0000x reference)
#include <cuda_runtime.h>
#include <cuda_fp16.h>
#include <stdint.h>

// ============================================================================
// QuaternionLSTM single step, h0=c0=0 (uh_* dead; forget-gate columns dropped):
//   Z = x @ W1 + b1  (W1 = quaternion-expanded wx, gates {i,o,a}, N=768)
//   H = sigmoid(z_o) * tanh( sigmoid(z_i) * tanh(z_a) )
//   out = H @ fco_w + fco_b
// fp16 mma.sync, f32 accum (rel_err ~4.6e-4). Column layout
// ncol = (h>>3)*24 + gate*8 + (h&7) keeps LSTM epilogue register-local.
// R7: hoisted cp.async pointers + LDSM offsets (kill per-chunk int division
// and address rebuilds that showed up as alu=22.7% / issue-bound in ncu).
// ============================================================================

#define B_DIM 32768
#define F_DIM 1024
#define H_DIM 256
#define N1G   768            // 3 gates x 256

__device__ __align__(16) __half g_xh[(size_t)B_DIM * F_DIM];
__device__ __align__(16) __half g_w1[F_DIM * N1G];           // [k][n_perm]
__device__ float g_b1[N1G];
__device__ __align__(16) __half g_h[(size_t)B_DIM * H_DIM];
__device__ __align__(16) __half g_f2[H_DIM * H_DIM];          // [k][n]

// ---------------------------------------------------------------------------
__device__ __forceinline__ uint32_t smem_u32(const void* p) {
    uint32_t a;
    asm("{ .reg .u64 t; cvta.to.shared.u64 t, %1; cvt.u32.u64 %0, t; }" : "=r"(a) : "l"(p));
    return a;
}

#define LDSM_X4(r, a) \
    asm volatile("ldmatrix.sync.aligned.m8n8.x4.shared.b16 {%0,%1,%2,%3}, [%4];" \
        : "=r"((r)[0]), "=r"((r)[1]), "=r"((r)[2]), "=r"((r)[3]) : "r"(a))
#define LDSM_X4T(r, a) \
    asm volatile("ldmatrix.sync.aligned.m8n8.x4.trans.shared.b16 {%0,%1,%2,%3}, [%4];" \
        : "=r"((r)[0]), "=r"((r)[1]), "=r"((r)[2]), "=r"((r)[3]) : "r"(a))
#define MMA_F16(d, a, b) \
    asm volatile("mma.sync.aligned.m16n8k16.row.col.f32.f16.f16.f32 " \
        "{%0,%1,%2,%3}, {%4,%5,%6,%7}, {%8,%9}, {%0,%1,%2,%3};" \
        : "+f"((d)[0]), "+f"((d)[1]), "+f"((d)[2]), "+f"((d)[3]) \
        : "r"((a)[0]), "r"((a)[1]), "r"((a)[2]), "r"((a)[3]), "r"((b)[0]), "r"((b)[1]))
#define CP_ASYNC16(dst, src) \
    asm volatile("cp.async.cg.shared.global [%0], [%1], 16;" :: "r"(dst), "l"(src) : "memory")
#define CP_COMMIT() asm volatile("cp.async.commit_group;" ::: "memory")
#define CP_WAIT(n)  asm volatile("cp.async.wait_group %0;" :: "n"(n) : "memory")

__device__ __forceinline__ float fsigm(float z) {
    return __fdividef(1.f, 1.f + __expf(-z));
}
__device__ __forceinline__ float ftanh(float x) {
    float xc = fminf(fmaxf(x, -15.f), 15.f);
    float e = __expf(2.f * xc);
    return __fdividef(e - 1.f, e + 1.f);
}

// ---------------------------------------------------------------------------
// Prep kernels
// ---------------------------------------------------------------------------
__global__ void split_x(const float* __restrict__ x) {
    size_t i = ((size_t)blockIdx.x * blockDim.x + threadIdx.x) * 4;
    float4 v = *(const float4*)(x + i);
    __half h[4] = {__float2half(v.x), __float2half(v.y),
                   __float2half(v.z), __float2half(v.w)};
    *(uint2*)&g_xh[i] = *(uint2*)h;
}

// grid (3, 1024): rem = bx*256+tid (0..767), f = by. No div by 768.
__global__ void build_w1(const float* __restrict__ wr, const float* __restrict__ wi,
                         const float* __restrict__ wj, const float* __restrict__ wk,
                         const float* __restrict__ bx) {
    int rem = blockIdx.x * blockDim.x + threadIdx.x;   // 0..767
    int f = blockIdx.y;
    int blk = rem / 24;
    int r24 = rem - blk * 24;
    int g1 = r24 >> 3, hh = r24 & 7;
    int h = blk * 8 + hh;
    int gate = g1 + 1;                      // skip forget gate (index 0)
    int qout = h >> 6, h4 = h & 63;
    int qin = f >> 8, f4 = f & 255;
    const int   ci[4][4] = {{0,1,2,3},{1,0,3,2},{2,3,0,1},{3,2,1,0}};
    const float sg[4][4] = {{ 1.f, 1.f, 1.f, 1.f},
                            {-1.f, 1.f, 1.f,-1.f},
                            {-1.f,-1.f, 1.f, 1.f},
                            {-1.f, 1.f,-1.f, 1.f}};
    const float* arr[4] = {wr, wi, wj, wk};
    float v = arr[ci[qin][qout]][gate * (256 * 64) + f4 * 64 + h4] * sg[qin][qout];
    g_w1[f * N1G + rem] = __float2half(v);
    if (f == 0) g_b1[rem] = bx[gate * H_DIM + h];
}

__global__ void split_fco(const float* __restrict__ w) {
    int idx = blockIdx.x * blockDim.x + threadIdx.x;  // over 65536, [k][n]
    g_f2[idx] = __float2half(w[idx]);
}

// ---------------------------------------------------------------------------
// GEMM1 + LSTM epilogue: CTA 128x192, K-chunk 32, 8 warps 2x4 (warp 64x48),
// 3-stage cp.async, 2 CTAs/SM. Hoisted addressing.
// SMEM/stage: A[128][pitch 80B] = 10240 + B[32][pitch 400B] = 12800
// ---------------------------------------------------------------------------
#define G1_BOFF   10240
#define G1_STAGE  23040
#define G1_SMEM   (3 * G1_STAGE)

__global__ __launch_bounds__(256, 2)
void gemm1_lstm() {
    constexpr int NSTEPS = F_DIM / 32;
    extern __shared__ __align__(128) char smem[];
    const uint32_t sb = smem_u32(smem);
    const int tid = threadIdx.x, lane = tid & 31, wid = tid >> 5;
    const int wm = wid >> 2, wn = wid & 3;
    const int rowBase = blockIdx.y * 128, colBase = blockIdx.x * 192;

    // ---- hoisted cp.async sources/dests (A: granules tid, tid+256; B: 3) ---
    // A granule g (0..511): row=g>>2, c16=g&3
    const __half* srcA0;
    uint32_t dstA0;
    {
        int row = tid >> 2, c16 = tid & 3;
        srcA0 = g_xh + (size_t)(rowBase + row) * F_DIM + c16 * 8;
        dstA0 = row * 80 + c16 * 16;
    }
    // A granule #2 differs by row+64: src +64*F_DIM halves, dst +64*80
    const __half* srcB[3];
    uint32_t dstB[3];
#pragma unroll
    for (int j = 0; j < 3; j++) {
        int gb = j * 256 + tid;             // 0..767
        int row = gb / 24, c16 = gb - row * 24;
        srcB[j] = g_w1 + (size_t)row * N1G + colBase + c16 * 8;
        dstB[j] = G1_BOFF + row * 400 + c16 * 16;
    }

    // ---- hoisted LDSM offsets -------------------------------------------
    const uint32_t aBase = (wm * 64 + (lane & 15)) * 80 + (lane >> 4) * 16;
    const uint32_t bBase = G1_BOFF + (lane & 15) * 400
                         + (wn * 48 + (lane >> 4) * 8) * 2;

    float acc[4][6][4];
#pragma unroll
    for (int a = 0; a < 4; a++)
#pragma unroll
        for (int b = 0; b < 6; b++)
#pragma unroll
            for (int c = 0; c < 4; c++) acc[a][b][c] = 0.f;

#pragma unroll
    for (int pre = 0; pre < 2; pre++) {     // prefetch chunks 0,1
        uint32_t base = sb + pre * G1_STAGE;
        CP_ASYNC16(base + dstA0, srcA0);
        CP_ASYNC16(base + dstA0 + 64 * 80, srcA0 + 64 * F_DIM);
#pragma unroll
        for (int j = 0; j < 3; j++) CP_ASYNC16(base + dstB[j], srcB[j]);
        CP_COMMIT();
        srcA0 += 32;
#pragma unroll
        for (int j = 0; j < 3; j++) srcB[j] += 32 * N1G;
    }

#pragma unroll 1
    for (int s = 0; s < NSTEPS; s++) {
        if (s + 1 < NSTEPS) CP_WAIT(1); else CP_WAIT(0);
        __syncthreads();
        if (s + 2 < NSTEPS) {
            uint32_t base = sb + ((s + 2) % 3) * G1_STAGE;
            CP_ASYNC16(base + dstA0, srcA0);
            CP_ASYNC16(base + dstA0 + 64 * 80, srcA0 + 64 * F_DIM);
#pragma unroll
            for (int j = 0; j < 3; j++) CP_ASYNC16(base + dstB[j], srcB[j]);
            CP_COMMIT();
            srcA0 += 32;
#pragma unroll
            for (int j = 0; j < 3; j++) srcB[j] += 32 * N1G;
        }

        uint32_t base = sb + (s % 3) * G1_STAGE;
#pragma unroll
        for (int kk = 0; kk < 2; kk++) {
            uint32_t bf[3][4];
#pragma unroll
            for (int p = 0; p < 3; p++)
                LDSM_X4T(bf[p], base + bBase + kk * 6400 + p * 32);
#pragma unroll
            for (int mi = 0; mi < 4; mi++) {
                uint32_t af[4];
                LDSM_X4(af, base + aBase + mi * 1280 + kk * 32);
#pragma unroll
                for (int ni = 0; ni < 6; ni++)
                    MMA_F16(acc[mi][ni], af, &bf[ni >> 1][(ni & 1) * 2]);
            }
        }
    }

    // --------------------- LSTM epilogue (register-local) -------------------
    const int c0 = 2 * (lane & 3);
    const int blk0 = (colBase / 24) + wn * 2;
#pragma unroll
    for (int b = 0; b < 2; b++) {
        const int cb = colBase + wn * 48 + b * 24;
        const int h0 = (blk0 + b) * 8 + c0;
        float bi0 = g_b1[cb + c0],      bi1 = g_b1[cb + c0 + 1];
        float bo0 = g_b1[cb + 8 + c0],  bo1 = g_b1[cb + 8 + c0 + 1];
        float ba0 = g_b1[cb + 16 + c0], ba1 = g_b1[cb + 16 + c0 + 1];
#pragma unroll
        for (int mi = 0; mi < 4; mi++) {
            int r0 = rowBase + wm * 64 + mi * 16 + (lane >> 2);
#pragma unroll
            for (int rr = 0; rr < 2; rr++) {
                float zi0 = acc[mi][3 * b + 0][rr * 2 + 0] + bi0;
                float zi1 = acc[mi][3 * b + 0][rr * 2 + 1] + bi1;
                float zo0 = acc[mi][3 * b + 1][rr * 2 + 0] + bo0;
                float zo1 = acc[mi][3 * b + 1][rr * 2 + 1] + bo1;
                float za0 = acc[mi][3 * b + 2][rr * 2 + 0] + ba0;
                float za1 = acc[mi][3 * b + 2][rr * 2 + 1] + ba1;
                float hv0 = fsigm(zo0) * ftanh(fsigm(zi0) * ftanh(za0));
                float hv1 = fsigm(zo1) * ftanh(fsigm(zi1) * ftanh(za1));
                size_t m = (size_t)(r0 + rr * 8);
                *(__half2*)&g_h[m * H_DIM + h0] =
                    __halves2half2(__float2half(hv0), __float2half(hv1));
            }
        }
    }
}

// ---------------------------------------------------------------------------
// GEMM2: out = H @ fco_w + fco_b. CTA 128x128, K=256, warp tile 64x32.
// SMEM/stage: A[128][80B] = 10240 + B[32][272B] = 8704
// ---------------------------------------------------------------------------
#define G2_BOFF   10240
#define G2_STAGE  18944
#define G2_SMEM   (3 * G2_STAGE)

__global__ __launch_bounds__(256, 2)
void gemm2(const float* __restrict__ biasg, float* __restrict__ outp) {
    constexpr int NB = H_DIM, NSTEPS = H_DIM / 32;
    extern __shared__ __align__(128) char smem[];
    const uint32_t sb = smem_u32(smem);
    const int tid = threadIdx.x, lane = tid & 31, wid = tid >> 5;
    const int wm = wid >> 2, wn = wid & 3;
    const int rowBase = blockIdx.y * 128, colBase = blockIdx.x * 128;

    const __half* srcA0;
    uint32_t dstA0;
    {
        int row = tid >> 2, c16 = tid & 3;
        srcA0 = g_h + (size_t)(rowBase + row) * H_DIM + c16 * 8;
        dstA0 = row * 80 + c16 * 16;
    }
    const __half* srcB[2];
    uint32_t dstB[2];
#pragma unroll
    for (int j = 0; j < 2; j++) {
        int gb = j * 256 + tid;
        int row = gb >> 4, c16 = gb & 15;
        srcB[j] = g_f2 + (size_t)row * NB + colBase + c16 * 8;
        dstB[j] = G2_BOFF + row * 272 + c16 * 16;
    }

    const uint32_t aBase = (wm * 64 + (lane & 15)) * 80 + (lane >> 4) * 16;
    const uint32_t bBase = G2_BOFF + (lane & 15) * 272
                         + (wn * 32 + (lane >> 4) * 8) * 2;

    float acc[4][4][4];
#pragma unroll
    for (int a = 0; a < 4; a++)
#pragma unroll
        for (int b = 0; b < 4; b++)
#pragma unroll
            for (int c = 0; c < 4; c++) acc[a][b][c] = 0.f;

#pragma unroll
    for (int pre = 0; pre < 2; pre++) {
        uint32_t base = sb + pre * G2_STAGE;
        CP_ASYNC16(base + dstA0, srcA0);
        CP_ASYNC16(base + dstA0 + 64 * 80, srcA0 + 64 * H_DIM);
#pragma unroll
        for (int j = 0; j < 2; j++) CP_ASYNC16(base + dstB[j], srcB[j]);
        CP_COMMIT();
        srcA0 += 32;
#pragma unroll
        for (int j = 0; j < 2; j++) srcB[j] += 32 * NB;
    }

#pragma unroll 1
    for (int s = 0; s < NSTEPS; s++) {
        if (s + 1 < NSTEPS) CP_WAIT(1); else CP_WAIT(0);
        __syncthreads();
        if (s + 2 < NSTEPS) {
            uint32_t base = sb + ((s + 2) % 3) * G2_STAGE;
            CP_ASYNC16(base + dstA0, srcA0);
            CP_ASYNC16(base + dstA0 + 64 * 80, srcA0 + 64 * H_DIM);
#pragma unroll
            for (int j = 0; j < 2; j++) CP_ASYNC16(base + dstB[j], srcB[j]);
            CP_COMMIT();
            srcA0 += 32;
#pragma unroll
            for (int j = 0; j < 2; j++) srcB[j] += 32 * NB;
        }

        uint32_t base = sb + (s % 3) * G2_STAGE;
#pragma unroll
        for (int kk = 0; kk < 2; kk++) {
            uint32_t bf[2][4];
#pragma unroll
            for (int p = 0; p < 2; p++)
                LDSM_X4T(bf[p], base + bBase + kk * 4352 + p * 32);
#pragma unroll
            for (int mi = 0; mi < 4; mi++) {
                uint32_t af[4];
                LDSM_X4(af, base + aBase + mi * 1280 + kk * 32);
#pragma unroll
                for (int ni = 0; ni < 4; ni++)
                    MMA_F16(acc[mi][ni], af, &bf[ni >> 1][(ni & 1) * 2]);
            }
        }
    }

#pragma unroll
    for (int mi = 0; mi < 4; mi++) {
        int r0 = rowBase + wm * 64 + mi * 16 + (lane >> 2);
#pragma unroll
        for (int ni = 0; ni < 4; ni++) {
            int col = colBase + wn * 32 + ni * 8 + (lane & 3) * 2;
            float b0 = biasg[col], b1 = biasg[col + 1];
            float2 o0 = {acc[mi][ni][0] + b0, acc[mi][ni][1] + b1};
            float2 o1 = {acc[mi][ni][2] + b0, acc[mi][ni][3] + b1};
            *(float2*)&outp[(size_t)r0 * NB + col] = o0;
            *(float2*)&outp[(size_t)(r0 + 8) * NB + col] = o1;
        }
    }
}

// ---------------------------------------------------------------------------
extern "C" void kernel_launch(void* const* d_in, const int* in_sizes, int n_in,
                              void* d_out, int out_size) {
    const float* x     = (const float*)d_in[0];
    const float* wx_r  = (const float*)d_in[1];
    const float* wx_i  = (const float*)d_in[2];
    const float* wx_j  = (const float*)d_in[3];
    const float* wx_k  = (const float*)d_in[4];
    const float* bx    = (const float*)d_in[5];
    const float* fco_w = (const float*)d_in[10];
    const float* fco_b = (const float*)d_in[11];
    float* out = (float*)d_out;

    split_x<<<(B_DIM * F_DIM / 4) / 256, 256>>>(x);
    build_w1<<<dim3(3, F_DIM), 256>>>(wx_r, wx_i, wx_j, wx_k, bx);
    split_fco<<<(H_DIM * H_DIM) / 256, 256>>>(fco_w);

    cudaFuncSetAttribute(gemm1_lstm,
                         cudaFuncAttributeMaxDynamicSharedMemorySize, G1_SMEM);
    cudaFuncSetAttribute(gemm2,
                         cudaFuncAttributeMaxDynamicSharedMemorySize, G2_SMEM);

    gemm1_lstm<<<dim3(N1G / 192, B_DIM / 128), 256, G1_SMEM>>>();
    gemm2<<<dim3(H_DIM / 128, B_DIM / 128), 256, G2_SMEM>>>(fco_b, out);
}

// round 8
// speedup vs baseline: 1.0157x; 1.0157x over previous
#include <cuda_runtime.h>
#include <cuda_fp16.h>
#include <stdint.h>

// ============================================================================
// QuaternionLSTM single step, h0=c0=0 (uh_* dead; forget-gate columns dropped):
//   Z = x @ W1 + b1  (W1 = quaternion-expanded wx, gates {i,o,a}, N=768)
//   H = sigmoid(z_o) * tanh( sigmoid(z_i) * tanh(z_a) )
//   out = H @ fco_w + fco_b
// fp16 mma.sync, f32 accum (rel_err ~4.6e-4). Column layout
// ncol = (h>>3)*24 + gate*8 + (h&7) keeps LSTM epilogue register-local.
// R8: K-chunk 64, 2-stage, ONE syncthreads per chunk (16 barriers vs 32) to
// amortize the per-chunk pipeline bubble that capped tensor util at ~51%.
// ============================================================================

#define B_DIM 32768
#define F_DIM 1024
#define H_DIM 256
#define N1G   768            // 3 gates x 256

__device__ __align__(16) __half g_xh[(size_t)B_DIM * F_DIM];
__device__ __align__(16) __half g_w1[F_DIM * N1G];           // [k][n_perm]
__device__ float g_b1[N1G];
__device__ __align__(16) __half g_h[(size_t)B_DIM * H_DIM];
__device__ __align__(16) __half g_f2[H_DIM * H_DIM];          // [k][n]

// ---------------------------------------------------------------------------
__device__ __forceinline__ uint32_t smem_u32(const void* p) {
    uint32_t a;
    asm("{ .reg .u64 t; cvta.to.shared.u64 t, %1; cvt.u32.u64 %0, t; }" : "=r"(a) : "l"(p));
    return a;
}

#define LDSM_X4(r, a) \
    asm volatile("ldmatrix.sync.aligned.m8n8.x4.shared.b16 {%0,%1,%2,%3}, [%4];" \
        : "=r"((r)[0]), "=r"((r)[1]), "=r"((r)[2]), "=r"((r)[3]) : "r"(a))
#define LDSM_X4T(r, a) \
    asm volatile("ldmatrix.sync.aligned.m8n8.x4.trans.shared.b16 {%0,%1,%2,%3}, [%4];" \
        : "=r"((r)[0]), "=r"((r)[1]), "=r"((r)[2]), "=r"((r)[3]) : "r"(a))
#define MMA_F16(d, a, b) \
    asm volatile("mma.sync.aligned.m16n8k16.row.col.f32.f16.f16.f32 " \
        "{%0,%1,%2,%3}, {%4,%5,%6,%7}, {%8,%9}, {%0,%1,%2,%3};" \
        : "+f"((d)[0]), "+f"((d)[1]), "+f"((d)[2]), "+f"((d)[3]) \
        : "r"((a)[0]), "r"((a)[1]), "r"((a)[2]), "r"((a)[3]), "r"((b)[0]), "r"((b)[1]))
#define CP_ASYNC16(dst, src) \
    asm volatile("cp.async.cg.shared.global [%0], [%1], 16;" :: "r"(dst), "l"(src) : "memory")
#define CP_COMMIT() asm volatile("cp.async.commit_group;" ::: "memory")
#define CP_WAIT(n)  asm volatile("cp.async.wait_group %0;" :: "n"(n) : "memory")

__device__ __forceinline__ float fsigm(float z) {
    return __fdividef(1.f, 1.f + __expf(-z));
}
__device__ __forceinline__ float ftanh(float x) {
    float xc = fminf(fmaxf(x, -15.f), 15.f);
    float e = __expf(2.f * xc);
    return __fdividef(e - 1.f, e + 1.f);
}

// ---------------------------------------------------------------------------
// Prep kernels
// ---------------------------------------------------------------------------
__global__ void split_x(const float* __restrict__ x) {
    size_t i = ((size_t)blockIdx.x * blockDim.x + threadIdx.x) * 4;
    float4 v = *(const float4*)(x + i);
    __half h[4] = {__float2half(v.x), __float2half(v.y),
                   __float2half(v.z), __float2half(v.w)};
    *(uint2*)&g_xh[i] = *(uint2*)h;
}

__global__ void build_w1(const float* __restrict__ wr, const float* __restrict__ wi,
                         const float* __restrict__ wj, const float* __restrict__ wk,
                         const float* __restrict__ bx) {
    int rem = blockIdx.x * blockDim.x + threadIdx.x;   // 0..767
    int f = blockIdx.y;
    int blk = rem / 24;
    int r24 = rem - blk * 24;
    int g1 = r24 >> 3, hh = r24 & 7;
    int h = blk * 8 + hh;
    int gate = g1 + 1;                      // skip forget gate (index 0)
    int qout = h >> 6, h4 = h & 63;
    int qin = f >> 8, f4 = f & 255;
    const int   ci[4][4] = {{0,1,2,3},{1,0,3,2},{2,3,0,1},{3,2,1,0}};
    const float sg[4][4] = {{ 1.f, 1.f, 1.f, 1.f},
                            {-1.f, 1.f, 1.f,-1.f},
                            {-1.f,-1.f, 1.f, 1.f},
                            {-1.f, 1.f,-1.f, 1.f}};
    const float* arr[4] = {wr, wi, wj, wk};
    float v = arr[ci[qin][qout]][gate * (256 * 64) + f4 * 64 + h4] * sg[qin][qout];
    g_w1[f * N1G + rem] = __float2half(v);
    if (f == 0) g_b1[rem] = bx[gate * H_DIM + h];
}

__global__ void split_fco(const float* __restrict__ w) {
    int idx = blockIdx.x * blockDim.x + threadIdx.x;
    g_f2[idx] = __float2half(w[idx]);
}

// ---------------------------------------------------------------------------
// GEMM1 + LSTM epilogue: CTA 128x192, K-chunk 64, 8 warps 2x4 (warp 64x48),
// 2-stage, one barrier per chunk, 2 CTAs/SM.
// SMEM/stage: A[128 rows][pitch 144B] = 18432 + B[64 rows][pitch 400B] = 25600
// ---------------------------------------------------------------------------
#define G1_BOFF   18432
#define G1_STAGE  44032
#define G1_SMEM   (2 * G1_STAGE)

__global__ __launch_bounds__(256, 2)
void gemm1_lstm() {
    constexpr int NSTEPS = F_DIM / 64;       // 16
    extern __shared__ __align__(128) char smem[];
    const uint32_t sb = smem_u32(smem);
    const int tid = threadIdx.x, lane = tid & 31, wid = tid >> 5;
    const int wm = wid >> 2, wn = wid & 3;
    const int rowBase = blockIdx.y * 128, colBase = blockIdx.x * 192;

    // ---- cp.async addressing (hoisted) ------------------------------------
    // A: 1024 granules (128 rows x 8 c16), 4/thread; rows tid>>3 + i*32
    const __half* srcA0 = g_xh + (size_t)(rowBase + (tid >> 3)) * F_DIM + (tid & 7) * 8;
    const uint32_t dstA0 = (tid >> 3) * 144 + (tid & 7) * 16;
    // B: 1536 granules (64 rows x 24 c16), 6/thread
    const __half* srcB[6];
    uint32_t dstB[6];
#pragma unroll
    for (int j = 0; j < 6; j++) {
        int gb = j * 256 + tid;
        int row = gb / 24, c16 = gb - row * 24;
        srcB[j] = g_w1 + (size_t)row * N1G + colBase + c16 * 8;
        dstB[j] = G1_BOFF + row * 400 + c16 * 16;
    }
    const __half* sA = srcA0;

    auto load_stage = [&](uint32_t base) {
#pragma unroll
        for (int i = 0; i < 4; i++)
            CP_ASYNC16(base + dstA0 + i * 4608, sA + (size_t)i * 32 * F_DIM);
#pragma unroll
        for (int j = 0; j < 6; j++)
            CP_ASYNC16(base + dstB[j], srcB[j]);
        CP_COMMIT();
        sA += 64;
#pragma unroll
        for (int j = 0; j < 6; j++) srcB[j] += 64 * N1G;
    };

    // ---- LDSM base offsets --------------------------------------------------
    const uint32_t aBase = (wm * 64 + (lane & 15)) * 144 + (lane >> 4) * 16;
    const uint32_t bBase = G1_BOFF + (lane & 15) * 400
                         + (wn * 48 + (lane >> 4) * 8) * 2;

    float acc[4][6][4];
#pragma unroll
    for (int a = 0; a < 4; a++)
#pragma unroll
        for (int b = 0; b < 6; b++)
#pragma unroll
            for (int c = 0; c < 4; c++) acc[a][b][c] = 0.f;

    load_stage(sb);                           // chunk 0 -> buf 0

#pragma unroll 1
    for (int s = 0; s < NSTEPS; s++) {
        CP_WAIT(0);
        __syncthreads();                      // all warps done reading buf (s-1)&1
        if (s + 1 < NSTEPS) load_stage(sb + ((s + 1) & 1) * G1_STAGE);

        uint32_t base = sb + (s & 1) * G1_STAGE;
#pragma unroll
        for (int kk = 0; kk < 4; kk++) {
            uint32_t bf[3][4];
#pragma unroll
            for (int p = 0; p < 3; p++)
                LDSM_X4T(bf[p], base + bBase + kk * 6400 + p * 32);
#pragma unroll
            for (int mi = 0; mi < 4; mi++) {
                uint32_t af[4];
                LDSM_X4(af, base + aBase + mi * 2304 + kk * 32);
#pragma unroll
                for (int ni = 0; ni < 6; ni++)
                    MMA_F16(acc[mi][ni], af, &bf[ni >> 1][(ni & 1) * 2]);
            }
        }
    }

    // --------------------- LSTM epilogue (register-local) -------------------
    const int c0 = 2 * (lane & 3);
    const int blk0 = (colBase / 24) + wn * 2;
#pragma unroll
    for (int b = 0; b < 2; b++) {
        const int cb = colBase + wn * 48 + b * 24;
        const int h0 = (blk0 + b) * 8 + c0;
        float bi0 = g_b1[cb + c0],      bi1 = g_b1[cb + c0 + 1];
        float bo0 = g_b1[cb + 8 + c0],  bo1 = g_b1[cb + 8 + c0 + 1];
        float ba0 = g_b1[cb + 16 + c0], ba1 = g_b1[cb + 16 + c0 + 1];
#pragma unroll
        for (int mi = 0; mi < 4; mi++) {
            int r0 = rowBase + wm * 64 + mi * 16 + (lane >> 2);
#pragma unroll
            for (int rr = 0; rr < 2; rr++) {
                float zi0 = acc[mi][3 * b + 0][rr * 2 + 0] + bi0;
                float zi1 = acc[mi][3 * b + 0][rr * 2 + 1] + bi1;
                float zo0 = acc[mi][3 * b + 1][rr * 2 + 0] + bo0;
                float zo1 = acc[mi][3 * b + 1][rr * 2 + 1] + bo1;
                float za0 = acc[mi][3 * b + 2][rr * 2 + 0] + ba0;
                float za1 = acc[mi][3 * b + 2][rr * 2 + 1] + ba1;
                float hv0 = fsigm(zo0) * ftanh(fsigm(zi0) * ftanh(za0));
                float hv1 = fsigm(zo1) * ftanh(fsigm(zi1) * ftanh(za1));
                size_t m = (size_t)(r0 + rr * 8);
                *(__half2*)&g_h[m * H_DIM + h0] =
                    __halves2half2(__float2half(hv0), __float2half(hv1));
            }
        }
    }
}

// ---------------------------------------------------------------------------
// GEMM2: out = H @ fco_w + fco_b. CTA 128x128, K=256 (8 chunks of 32),
// 3-stage, warp tile 64x32.
// ---------------------------------------------------------------------------
#define G2_BOFF   10240
#define G2_STAGE  18944
#define G2_SMEM   (3 * G2_STAGE)

__global__ __launch_bounds__(256, 2)
void gemm2(const float* __restrict__ biasg, float* __restrict__ outp) {
    constexpr int NB = H_DIM, NSTEPS = H_DIM / 32;
    extern __shared__ __align__(128) char smem[];
    const uint32_t sb = smem_u32(smem);
    const int tid = threadIdx.x, lane = tid & 31, wid = tid >> 5;
    const int wm = wid >> 2, wn = wid & 3;
    const int rowBase = blockIdx.y * 128, colBase = blockIdx.x * 128;

    const __half* srcA0 = g_h + (size_t)(rowBase + (tid >> 2)) * H_DIM + (tid & 3) * 8;
    const uint32_t dstA0 = (tid >> 2) * 80 + (tid & 3) * 16;
    const __half* srcB[2];
    uint32_t dstB[2];
#pragma unroll
    for (int j = 0; j < 2; j++) {
        int gb = j * 256 + tid;
        int row = gb >> 4, c16 = gb & 15;
        srcB[j] = g_f2 + (size_t)row * NB + colBase + c16 * 8;
        dstB[j] = G2_BOFF + row * 272 + c16 * 16;
    }
    const __half* sA = srcA0;

    auto load_stage = [&](uint32_t base) {
        CP_ASYNC16(base + dstA0, sA);
        CP_ASYNC16(base + dstA0 + 64 * 80, sA + 64 * H_DIM);
#pragma unroll
        for (int j = 0; j < 2; j++) CP_ASYNC16(base + dstB[j], srcB[j]);
        CP_COMMIT();
        sA += 32;
#pragma unroll
        for (int j = 0; j < 2; j++) srcB[j] += 32 * NB;
    };

    const uint32_t aBase = (wm * 64 + (lane & 15)) * 80 + (lane >> 4) * 16;
    const uint32_t bBase = G2_BOFF + (lane & 15) * 272
                         + (wn * 32 + (lane >> 4) * 8) * 2;

    float acc[4][4][4];
#pragma unroll
    for (int a = 0; a < 4; a++)
#pragma unroll
        for (int b = 0; b < 4; b++)
#pragma unroll
            for (int c = 0; c < 4; c++) acc[a][b][c] = 0.f;

    load_stage(sb);
    load_stage(sb + G2_STAGE);

#pragma unroll 1
    for (int s = 0; s < NSTEPS; s++) {
        if (s + 1 < NSTEPS) CP_WAIT(1); else CP_WAIT(0);
        __syncthreads();
        if (s + 2 < NSTEPS) load_stage(sb + ((s + 2) % 3) * G2_STAGE);

        uint32_t base = sb + (s % 3) * G2_STAGE;
#pragma unroll
        for (int kk = 0; kk < 2; kk++) {
            uint32_t bf[2][4];
#pragma unroll
            for (int p = 0; p < 2; p++)
                LDSM_X4T(bf[p], base + bBase + kk * 4352 + p * 32);
#pragma unroll
            for (int mi = 0; mi < 4; mi++) {
                uint32_t af[4];
                LDSM_X4(af, base + aBase + mi * 1280 + kk * 32);
#pragma unroll
                for (int ni = 0; ni < 4; ni++)
                    MMA_F16(acc[mi][ni], af, &bf[ni >> 1][(ni & 1) * 2]);
            }
        }
    }

#pragma unroll
    for (int mi = 0; mi < 4; mi++) {
        int r0 = rowBase + wm * 64 + mi * 16 + (lane >> 2);
#pragma unroll
        for (int ni = 0; ni < 4; ni++) {
            int col = colBase + wn * 32 + ni * 8 + (lane & 3) * 2;
            float b0 = biasg[col], b1 = biasg[col + 1];
            float2 o0 = {acc[mi][ni][0] + b0, acc[mi][ni][1] + b1};
            float2 o1 = {acc[mi][ni][2] + b0, acc[mi][ni][3] + b1};
            *(float2*)&outp[(size_t)r0 * NB + col] = o0;
            *(float2*)&outp[(size_t)(r0 + 8) * NB + col] = o1;
        }
    }
}

// ---------------------------------------------------------------------------
extern "C" void kernel_launch(void* const* d_in, const int* in_sizes, int n_in,
                              void* d_out, int out_size) {
    const float* x     = (const float*)d_in[0];
    const float* wx_r  = (const float*)d_in[1];
    const float* wx_i  = (const float*)d_in[2];
    const float* wx_j  = (const float*)d_in[3];
    const float* wx_k  = (const float*)d_in[4];
    const float* bx    = (const float*)d_in[5];
    const float* fco_w = (const float*)d_in[10];
    const float* fco_b = (const float*)d_in[11];
    float* out = (float*)d_out;

    split_x<<<(B_DIM * F_DIM / 4) / 256, 256>>>(x);
    build_w1<<<dim3(3, F_DIM), 256>>>(wx_r, wx_i, wx_j, wx_k, bx);
    split_fco<<<(H_DIM * H_DIM) / 256, 256>>>(fco_w);

    cudaFuncSetAttribute(gemm1_lstm,
                         cudaFuncAttributeMaxDynamicSharedMemorySize, G1_SMEM);
    cudaFuncSetAttribute(gemm2,
                         cudaFuncAttributeMaxDynamicSharedMemorySize, G2_SMEM);

    gemm1_lstm<<<dim3(N1G / 192, B_DIM / 128), 256, G1_SMEM>>>();
    gemm2<<<dim3(H_DIM / 128, B_DIM / 128), 256, G2_SMEM>>>(fco_b, out);
}